// round 4
// baseline (speedup 1.0000x reference)
#include <cuda_runtime.h>

// Problem constants
#define HH   64
#define WW   64
#define CIN  48
#define OCC  192   // 4*F gate channels
#define BB   4
#define TT   16
#define NF   48

// Dynamic smem: max( patch 10*10*48 + weights 48*192 , z 64*192 ) floats
#define SMEM_FLOATS 14016
#define SMEM_BYTES  (SMEM_FLOATS * 4)

// Scratch (device globals -- no runtime allocation allowed)
__device__ float g_zx[(size_t)BB * TT * HH * WW * OCC];  // precomputed conv(x,Wx)+b per layer
__device__ float g_h1[(size_t)BB * TT * HH * WW * NF];   // layer-1 output sequence
__device__ float g_hA[(size_t)BB * HH * WW * NF];        // recurrent h (double-buffered)
__device__ float g_hB[(size_t)BB * HH * WW * NF];
__device__ float g_c [(size_t)BB * HH * WW * NF];        // cell state

__global__ void zero_state_kernel() {
    size_t n = (size_t)BB * HH * WW * NF;
    for (size_t i = (size_t)blockIdx.x * blockDim.x + threadIdx.x; i < n;
         i += (size_t)gridDim.x * blockDim.x) {
        g_hA[i] = 0.f;
        g_c[i]  = 0.f;
    }
}

__device__ __forceinline__ float hsig(float x) {
    // Keras hard_sigmoid: clip(x/6 + 0.5, 0, 1)
    return __saturatef(x * (1.0f / 6.0f) + 0.5f);
}

// Load 10x10x48 input patch (zero-padded) into smem, optionally applying BN scale/shift.
// NOTE: BN must be applied ONLY to in-bounds pixels -- the conv pads the
// already-normalized tensor with exact zeros.
template <bool BN>
__device__ __forceinline__ void load_patch(const float* __restrict__ src,  // image base [H,W,48]
                                           float* s_in, int gy0, int gx0, int tid,
                                           const float* s_scale, const float* s_shift) {
    for (int p = tid; p < 1200; p += 256) {  // 100 pixels * 12 float4
        int pix = p / 12, cv = p - pix * 12;
        int py = pix / 10, px = pix - py * 10;
        int gy = gy0 + py, gx = gx0 + px;
        float4 v = make_float4(0.f, 0.f, 0.f, 0.f);
        if ((unsigned)gy < HH && (unsigned)gx < WW) {
            v = *(const float4*)(src + ((size_t)gy * WW + gx) * CIN + cv * 4);
            if (BN) {
                int c = cv * 4;
                v.x = v.x * s_scale[c + 0] + s_shift[c + 0];
                v.y = v.y * s_scale[c + 1] + s_shift[c + 1];
                v.z = v.z * s_scale[c + 2] + s_shift[c + 2];
                v.w = v.w * s_scale[c + 3] + s_shift[c + 3];
            }
        }
        ((float4*)s_in)[p] = v;
    }
}

// Shared conv core: accumulate 3x3x48 -> 192 for this thread's 4 spatial x 12 oc tile.
__device__ __forceinline__ void conv_accum(const float* __restrict__ Wg,  // [3,3,48,192]
                                           const float* s_in, float* s_w,
                                           float acc[4][12],
                                           int tid, int sy, int sx0, int oc0) {
#pragma unroll 1
    for (int kk = 0; kk < 9; kk++) {
        __syncthreads();
        // stage 48x192 weight slice for this (kh,kw)
        const float4* wsrc = (const float4*)(Wg + (size_t)kk * CIN * OCC);
        float4* wdst = (float4*)s_w;
#pragma unroll
        for (int p = 0; p < 9; p++) wdst[tid + p * 256] = wsrc[tid + p * 256];
        __syncthreads();

        int kh = kk / 3, kw = kk - kh * 3;
        const float* inrow = s_in + ((sy + kh) * 10 + sx0 + kw) * CIN;
        const float* wbase = s_w + oc0;
#pragma unroll 4
        for (int c = 0; c < CIN; c++) {
            float iv0 = inrow[c];
            float iv1 = inrow[c + CIN];
            float iv2 = inrow[c + 2 * CIN];
            float iv3 = inrow[c + 3 * CIN];
            const float4* wc4 = (const float4*)(wbase + c * OCC);
            float4 wa = wc4[0], wb = wc4[1], wc = wc4[2];
            float wv[12] = {wa.x, wa.y, wa.z, wa.w, wb.x, wb.y, wb.z, wb.w,
                            wc.x, wc.y, wc.z, wc.w};
#pragma unroll
            for (int j = 0; j < 12; j++) {
                acc[0][j] += iv0 * wv[j];
                acc[1][j] += iv1 * wv[j];
                acc[2][j] += iv2 * wv[j];
                acc[3][j] += iv3 * wv[j];
            }
        }
    }
}

// conv(input, Wx) + b over all 64 (b,t) images. BN=true reads g_h1 and applies BN first.
template <bool BN>
__global__ void __launch_bounds__(256) convx_kernel(
    const float* __restrict__ xin, const float* __restrict__ Wx,
    const float* __restrict__ bias,
    const float* __restrict__ gamma, const float* __restrict__ beta,
    const float* __restrict__ mean, const float* __restrict__ var) {
    extern __shared__ float sm[];
    float* s_in = sm;          // 4800 floats
    float* s_w  = sm + 4800;   // 9216 floats
    __shared__ float s_scale[CIN], s_shift[CIN];

    int tid = threadIdx.x;
    int img = blockIdx.z;  // b*T + t
    int gy0 = blockIdx.y * 8 - 1, gx0 = blockIdx.x * 8 - 1;

    if (BN) {
        if (tid < CIN) {
            float sc = gamma[tid] * rsqrtf(var[tid] + 1e-3f);
            s_scale[tid] = sc;
            s_shift[tid] = beta[tid] - mean[tid] * sc;
        }
        __syncthreads();
    }
    const float* src = BN ? (g_h1 + (size_t)img * HH * WW * NF)
                          : (xin + (size_t)img * HH * WW * CIN);
    load_patch<BN>(src, s_in, gy0, gx0, tid, s_scale, s_shift);

    int og = tid & 15, sg = tid >> 4;
    int oc0 = og * 12;
    int sy = sg >> 1, sx0 = (sg & 1) * 4;

    float acc[4][12];
#pragma unroll
    for (int j = 0; j < 12; j++) {
        float bv = bias[oc0 + j];
        acc[0][j] = bv; acc[1][j] = bv; acc[2][j] = bv; acc[3][j] = bv;
    }
    conv_accum(Wx, s_in, s_w, acc, tid, sy, sx0, oc0);

#pragma unroll
    for (int i = 0; i < 4; i++) {
        int y = blockIdx.y * 8 + sy, x = blockIdx.x * 8 + sx0 + i;
        float* dst = g_zx + (((size_t)img * HH + y) * WW + x) * OCC + oc0;
        float4* d4 = (float4*)dst;
        d4[0] = make_float4(acc[i][0], acc[i][1], acc[i][2], acc[i][3]);
        d4[1] = make_float4(acc[i][4], acc[i][5], acc[i][6], acc[i][7]);
        d4[2] = make_float4(acc[i][8], acc[i][9], acc[i][10], acc[i][11]);
    }
}

// One recurrent step: z = zx[t] + conv(h,Wh); gates; update c,h.
// LAYER 1 -> write h to g_h1 sequence; LAYER 2 -> write out = x + h.
template <int LAYER>
__global__ void __launch_bounds__(256) step_kernel(
    const float* __restrict__ Wh, int t, int parity,
    const float* __restrict__ xres, float* __restrict__ out) {
    extern __shared__ float sm[];
    float* s_in = sm;
    float* s_w  = sm + 4800;
    float* s_z  = sm;  // reuses patch+weight region after conv

    int tid = threadIdx.x;
    int b = blockIdx.z;
    int gy0 = blockIdx.y * 8 - 1, gx0 = blockIdx.x * 8 - 1;

    const float* hin = parity ? g_hB : g_hA;
    float* hout      = parity ? g_hA : g_hB;

    load_patch<false>(hin + (size_t)b * HH * WW * NF, s_in, gy0, gx0, tid, nullptr, nullptr);

    int og = tid & 15, sg = tid >> 4;
    int oc0 = og * 12;
    int sy = sg >> 1, sx0 = (sg & 1) * 4;

    float acc[4][12];
#pragma unroll
    for (int i = 0; i < 4; i++)
#pragma unroll
        for (int j = 0; j < 12; j++) acc[i][j] = 0.f;

    conv_accum(Wh, s_in, s_w, acc, tid, sy, sx0, oc0);

    __syncthreads();  // all smem reads done; safe to overwrite with z
#pragma unroll
    for (int i = 0; i < 4; i++) {
        int s = sy * 8 + sx0 + i;
        float4* d4 = (float4*)(s_z + s * OCC + oc0);
        d4[0] = make_float4(acc[i][0], acc[i][1], acc[i][2], acc[i][3]);
        d4[1] = make_float4(acc[i][4], acc[i][5], acc[i][6], acc[i][7]);
        d4[2] = make_float4(acc[i][8], acc[i][9], acc[i][10], acc[i][11]);
    }
    __syncthreads();

    int imgt = b * TT + t;
#pragma unroll 1
    for (int k = 0; k < 12; k++) {
        int e = tid + k * 256;         // 0..3071: 64 spatial x 48 f-channels
        int s = e / 48, f = e - s * 48;
        int yy = gy0 + 1 + (s >> 3);
        int xx = gx0 + 1 + (s & 7);
        size_t zoff = (((size_t)imgt * HH + yy) * WW + xx) * OCC;
        const float* zx = g_zx + zoff;
        float zi = s_z[s * OCC + f]          + zx[f];
        float zf = s_z[s * OCC + f + NF]     + zx[f + NF];
        float zg = s_z[s * OCC + f + 2 * NF] + zx[f + 2 * NF];
        float zo = s_z[s * OCC + f + 3 * NF] + zx[f + 3 * NF];

        size_t hoff = (((size_t)b * HH + yy) * WW + xx) * NF + f;
        float cold = g_c[hoff];
        float cn = hsig(zf) * cold + hsig(zi) * tanhf(zg);
        float hn = hsig(zo) * tanhf(cn);
        g_c[hoff]  = cn;
        hout[hoff] = hn;

        size_t ooff = (((size_t)imgt * HH + yy) * WW + xx) * NF + f;
        if (LAYER == 1)
            g_h1[ooff] = hn;
        else
            out[ooff] = xres[ooff] + hn;
    }
}

extern "C" void kernel_launch(void* const* d_in, const int* in_sizes, int n_in,
                              void* d_out, int out_size) {
    const float* x     = (const float*)d_in[0];
    const float* Wx1   = (const float*)d_in[1];
    const float* Wh1   = (const float*)d_in[2];
    const float* b1    = (const float*)d_in[3];
    const float* Wx2   = (const float*)d_in[4];
    const float* Wh2   = (const float*)d_in[5];
    const float* b2    = (const float*)d_in[6];
    const float* gamma = (const float*)d_in[7];
    const float* beta  = (const float*)d_in[8];
    const float* mean  = (const float*)d_in[9];
    const float* var   = (const float*)d_in[10];
    float* out = (float*)d_out;

    cudaFuncSetAttribute((const void*)convx_kernel<false>,
                         cudaFuncAttributeMaxDynamicSharedMemorySize, SMEM_BYTES);
    cudaFuncSetAttribute((const void*)convx_kernel<true>,
                         cudaFuncAttributeMaxDynamicSharedMemorySize, SMEM_BYTES);
    cudaFuncSetAttribute((const void*)step_kernel<1>,
                         cudaFuncAttributeMaxDynamicSharedMemorySize, SMEM_BYTES);
    cudaFuncSetAttribute((const void*)step_kernel<2>,
                         cudaFuncAttributeMaxDynamicSharedMemorySize, SMEM_BYTES);

    dim3 blk(256);
    dim3 gridx(8, 8, BB * TT);  // all (b,t) images
    dim3 grids(8, 8, BB);       // one recurrent step

    // ---- Layer 1 ----
    zero_state_kernel<<<256, 256>>>();
    convx_kernel<false><<<gridx, blk, SMEM_BYTES>>>(x, Wx1, b1,
                                                    nullptr, nullptr, nullptr, nullptr);
    for (int t = 0; t < TT; t++)
        step_kernel<1><<<grids, blk, SMEM_BYTES>>>(Wh1, t, t & 1, nullptr, nullptr);

    // ---- Layer 2 (BN folded into Zx conv's input load) ----
    zero_state_kernel<<<256, 256>>>();
    convx_kernel<true><<<gridx, blk, SMEM_BYTES>>>(nullptr, Wx2, b2,
                                                   gamma, beta, mean, var);
    for (int t = 0; t < TT; t++)
        step_kernel<2><<<grids, blk, SMEM_BYTES>>>(Wh2, t, t & 1, x, out);
}